// round 1
// baseline (speedup 1.0000x reference)
#include <cuda_runtime.h>
#include <math.h>

#define NI 32     // images
#define NB 128    // captions
#define RR 128    // reduced channels
#define LL 1024   // latent
#define TT 64     // initial time

// ---------------- device scratch (static globals; no allocation) ----------------
__device__ float  g_cap_red[NB*RR*TT];                 // [b][o][64]   4 MB
__device__ float  g_img_global[NI*LL];
__device__ float  g_inorm[NI];
__device__ float  g_img_vec[NI*RR];
__device__ float  g_kern[NI*2*128*128];                // [(i*2+j)][cik][o]  4 MB
__device__ float  g_caWT[2*128*128];                   // [j][cik][o]
__device__ float  g_c1WT[2*256*128];                   // [j][ch][o]
__device__ float  g_WfcT[128*1024];                    // [c][l]
__device__ double g_stats[NI*256*2];                   // per-image per-channel sum/sumsq
__device__ float  g_h[(size_t)NI*NB*256*64];           // conv outputs (px|ax), 268 MB
__device__ float  g_x[(size_t)NI*NB*128*64];           // block activations, 134 MB
__device__ float  g_y[(size_t)NI*NB*1024];             // max-pooled pre-norm, 17 MB

// ---------------- stage 1: image prep (mean, norm, hypernet base) ----------------
__global__ __launch_bounds__(256) void k_img_prep(const float* __restrict__ img_embed,
                                                  const float* __restrict__ W_ri,
                                                  const float* __restrict__ b_ri) {
    __shared__ float gsh[LL];
    __shared__ float red[256];
    int i = blockIdx.x, tid = threadIdx.x;
    float ssq = 0.f;
    for (int c = tid; c < LL; c += 256) {
        float s = 0.f;
        #pragma unroll
        for (int t = 0; t < 36; t++) s += img_embed[((size_t)i*36 + t)*LL + c];
        s *= (1.0f/36.0f);
        gsh[c] = s;
        g_img_global[i*LL + c] = s;
        ssq += s*s;
    }
    red[tid] = ssq; __syncthreads();
    for (int s = 128; s > 0; s >>= 1) { if (tid < s) red[tid] += red[tid+s]; __syncthreads(); }
    if (tid == 0) g_inorm[i] = sqrtf(red[0]);
    if (tid < RR) {
        int o = tid;
        float acc = b_ri[o];
        const float* w = W_ri + (size_t)o * LL;
        for (int c = 0; c < LL; c++) acc = fmaf(w[c], gsh[c], acc);
        g_img_vec[i*RR + o] = acc;
    }
}

// ---------------- stage 2: caption reduction (1x1 conv 300->128) ----------------
__global__ __launch_bounds__(256) void k_cap_red(const float* __restrict__ cap_embed,
                                                 const float* __restrict__ W_rt,
                                                 const float* __restrict__ b_rt) {
    extern __shared__ float sm[];
    float* ce = sm;                      // [c 300][t 64] transposed cache
    int b = blockIdx.x, tid = threadIdx.x;
    for (int idx = tid; idx < 300*TT; idx += 256) {
        int c = idx >> 6, t = idx & 63;
        ce[idx] = cap_embed[(size_t)b*TT*300 + t*300 + c];
    }
    __syncthreads();
    for (int q = tid; q < RR*16; q += 256) {
        int o = q >> 4, tq = (q & 15) * 4;
        float a0 = 0.f, a1 = 0.f, a2 = 0.f, a3 = 0.f;
        const float* w = W_rt + o*300;
        for (int c = 0; c < 300; c++) {
            float wv = w[c];
            float4 x4 = *(const float4*)(ce + c*TT + tq);
            a0 = fmaf(wv, x4.x, a0); a1 = fmaf(wv, x4.y, a1);
            a2 = fmaf(wv, x4.z, a2); a3 = fmaf(wv, x4.w, a3);
        }
        float bo = b_rt[o];
        float* dst = g_cap_red + ((size_t)b*RR + o)*TT + tq;
        dst[0] = a0 + bo; dst[1] = a1 + bo; dst[2] = a2 + bo; dst[3] = a3 + bo;
    }
}

// ---------------- stage 3: hypernet kernel generation + weight BN ----------------
__global__ __launch_bounds__(256) void k_gen(const float* __restrict__ mk_W,
                                             const float* __restrict__ mk_b,
                                             const float* __restrict__ wn_g,
                                             const float* __restrict__ wn_b) {
    extern __shared__ float sm[];
    float* base = sm;          // 128
    float* kraw = sm + 128;    // 16384
    int i = blockIdx.x >> 1, j = blockIdx.x & 1, tid = threadIdx.x;
    if (tid < RR) base[tid] = g_img_vec[i*RR + tid];
    __syncthreads();
    for (int f = tid; f < 16384; f += 256) {
        float acc = mk_b[j*16384 + f];
        const float* w = mk_W + ((size_t)j*16384 + f)*128;
        #pragma unroll 4
        for (int c = 0; c < 128; c++) acc = fmaf(w[c], base[c], acc);
        kraw[f] = acc;
    }
    __syncthreads();
    if (tid < RR) {
        int o = tid;
        const float* kr = kraw + o*128;
        float s = 0.f, s2 = 0.f;
        for (int c = 0; c < 128; c++) { float v = kr[c]; s += v; s2 += v*v; }
        float m   = s * (1.f/128.f);
        float var = s2 * (1.f/128.f) - m*m;
        float a   = wn_g[j*RR+o] * rsqrtf(var + 1e-5f);
        float bb  = wn_b[j*RR+o] - a*m;
        float* dst = g_kern + ((size_t)(i*2+j))*16384;    // [cik][o]
        for (int cik = 0; cik < 128; cik++) dst[cik*128 + o] = fmaf(a, kr[cik], bb);
    }
}

// ---------------- stage 4: weight transposes (coalesced consumers) ----------------
__global__ void k_transpose(const float* __restrict__ W_fc,
                            const float* __restrict__ c1_W,
                            const float* __restrict__ ca_W) {
    const int N1 = 128*1024, N2 = 2*256*128, N3 = 2*128*128;
    for (int t = blockIdx.x*blockDim.x + threadIdx.x; t < N1+N2+N3; t += gridDim.x*blockDim.x) {
        if (t < N1) {
            int c = t >> 10, l = t & 1023;
            g_WfcT[t] = W_fc[l*128 + c];
        } else if (t < N1+N2) {
            int u = t - N1;
            int j = u >> 15; int v = u & 32767; int ch = v >> 7, o = v & 127;
            g_c1WT[u] = c1_W[(j*128 + o)*256 + ch];
        } else {
            int u = t - N1 - N2;
            int j = u >> 14; int v = u & 16383; int cik = v >> 7, o = v & 127;
            g_caWT[u] = ca_W[(j*128 + o)*128 + cik];
        }
    }
}

__global__ void k_zero_stats() {
    int idx = blockIdx.x*blockDim.x + threadIdx.x;
    if (idx < NI*256*2) g_stats[idx] = 0.0;
}

// ---------------- stage 5: grouped convs (px = hypernet, ax = static) + BN stats ----
// thread owns channel o for both px and ax (shared input window), 7 t's per chunk
template<int TOUT>
__global__ __launch_bounds__(256) void k_conv(int j) {
    extern __shared__ float sm[];
    float* xs  = sm;                    // [128][64]
    float* wpx = sm + 8192;             // [cik][o]
    float* wax = sm + 8192 + 16384;     // [cik][o]
    int b = blockIdx.x, i = blockIdx.y, tid = threadIdx.x;
    const float* xin = (j == 0) ? (g_cap_red + (size_t)b*8192)
                                : (g_x + ((size_t)i*NB + b)*8192);
    for (int idx = tid; idx < 8192; idx += 256) xs[idx] = xin[idx];
    const float* kp = g_kern + (size_t)(i*2 + j)*16384;
    const float* ka = g_caWT + (size_t)j*16384;
    for (int idx = tid; idx < 16384; idx += 256) { wpx[idx] = kp[idx]; wax[idx] = ka[idx]; }
    __syncthreads();

    int o = tid & 127, th = tid >> 7;
    int grp = o >> 6;
    const float* xg = xs + grp*64*64;
    float sp = 0.f, sp2 = 0.f, sa = 0.f, sa2 = 0.f;
    for (int chunk = th; chunk*7 < TOUT; chunk += 2) {
        int t0 = chunk*7;
        int nt = TOUT - t0; if (nt > 7) nt = 7;
        float accP[7], accA[7];
        #pragma unroll
        for (int t = 0; t < 7; t++) { accP[t] = 0.f; accA[t] = 0.f; }
        #pragma unroll 4
        for (int ci = 0; ci < 64; ci++) {
            const float* xr = xg + ci*64 + t0;
            float xv[8];
            #pragma unroll
            for (int u = 0; u < 8; u++) xv[u] = xr[u];
            float wp0 = wpx[(ci*2  )*128 + o], wp1 = wpx[(ci*2+1)*128 + o];
            float wa0 = wax[(ci*2  )*128 + o], wa1 = wax[(ci*2+1)*128 + o];
            #pragma unroll
            for (int t = 0; t < 7; t++) {
                accP[t] = fmaf(wp0, xv[t], fmaf(wp1, xv[t+1], accP[t]));
                accA[t] = fmaf(wa0, xv[t], fmaf(wa1, xv[t+1], accA[t]));
            }
        }
        float* hp = g_h + (((size_t)(i*NB + b)*256 + o)*64) + t0;
        float* ha = hp + 128*64;
        #pragma unroll
        for (int t = 0; t < 7; t++) if (t < nt) {
            hp[t] = accP[t]; ha[t] = accA[t];
            sp += accP[t]; sp2 += accP[t]*accP[t];
            sa += accA[t]; sa2 += accA[t]*accA[t];
        }
    }
    double* st = g_stats + (size_t)i*512;
    atomicAdd(st + o*2 + 0,        (double)sp);
    atomicAdd(st + o*2 + 1,        (double)sp2);
    atomicAdd(st + (128+o)*2 + 0,  (double)sa);
    atomicAdd(st + (128+o)*2 + 1,  (double)sa2);
}

// ---------------- stage 6: BN+ReLU fused into 1x1 mixing conv (c1) ----------------
template<int TOUT>
__global__ __launch_bounds__(256) void k_c1(const float* __restrict__ bn_g,
                                            const float* __restrict__ bn_b,
                                            const float* __restrict__ c1_b, int j) {
    extern __shared__ float sm[];
    float* hs = sm;                       // [256][64]
    float* ws = sm + 16384;               // [ch][o]
    float* aa = sm + 16384 + 32768;       // 256
    float* bb = aa + 256;                 // 256
    int b = blockIdx.x, i = blockIdx.y, tid = threadIdx.x;
    {
        double s  = g_stats[i*512 + tid*2];
        double s2 = g_stats[i*512 + tid*2 + 1];
        double n  = (double)(NB*TOUT);
        float m   = (float)(s / n);
        float var = (float)(s2 / n) - m*m;
        float a   = bn_g[j*256 + tid] * rsqrtf(var + 1e-5f);
        aa[tid] = a;
        bb[tid] = bn_b[j*256 + tid] - a*m;
    }
    __syncthreads();
    const float* hsrc = g_h + (size_t)(i*NB + b)*256*64;
    for (int idx = tid; idx < 256*64; idx += 256) {
        int ch = idx >> 6, t = idx & 63;
        float v = fmaf(aa[ch], hsrc[idx], bb[ch]);
        hs[idx] = (t < TOUT) ? fmaxf(v, 0.f) : 0.f;
    }
    const float* wsrc = g_c1WT + j*32768;
    for (int idx = tid; idx < 32768; idx += 256) ws[idx] = wsrc[idx];
    __syncthreads();

    int og = tid & 31, tg = tid >> 5;     // 32 o-groups x 8 t-groups
    float* xout = g_x + (size_t)(i*NB + b)*8192;
    #pragma unroll
    for (int half = 0; half < 2; half++) {
        int tb = tg*4 + half*32;
        float acc[4][4];
        #pragma unroll
        for (int a1 = 0; a1 < 4; a1++)
            #pragma unroll
            for (int a2 = 0; a2 < 4; a2++) acc[a1][a2] = 0.f;
        for (int ch = 0; ch < 256; ch++) {
            float h0 = hs[ch*64 + tb    ], h1 = hs[ch*64 + tb + 1];
            float h2 = hs[ch*64 + tb + 2], h3 = hs[ch*64 + tb + 3];
            #pragma unroll
            for (int io = 0; io < 4; io++) {
                float w = ws[ch*128 + og + 32*io];
                acc[io][0] = fmaf(w, h0, acc[io][0]);
                acc[io][1] = fmaf(w, h1, acc[io][1]);
                acc[io][2] = fmaf(w, h2, acc[io][2]);
                acc[io][3] = fmaf(w, h3, acc[io][3]);
            }
        }
        #pragma unroll
        for (int io = 0; io < 4; io++) {
            int o = og + 32*io;
            float cb = c1_b[j*128 + o];
            #pragma unroll
            for (int tt = 0; tt < 4; tt++) {
                int t = tb + tt;
                if (t < TOUT) xout[o*64 + t] = acc[io][tt] + cb;
            }
        }
    }
}

// ---------------- stage 7: W_fc GEMM fused with max-over-time ----------------
__global__ __launch_bounds__(256) void k_fc_max(const float* __restrict__ b_fc) {
    extern __shared__ float sm[];
    float* wts = sm;                  // [c 128][ll 128]
    float* xs  = sm + 16384;          // [c 128][t 64]
    float* red = sm + 16384 + 8192;   // [tg 8][ll 128]
    int lt = blockIdx.x, b = blockIdx.y, i = blockIdx.z, tid = threadIdx.x;
    for (int idx = tid; idx < 16384; idx += 256) {
        int c = idx >> 7, ll = idx & 127;
        wts[idx] = g_WfcT[c*1024 + lt*128 + ll];
    }
    const float* xin = g_x + (size_t)(i*NB + b)*8192;
    for (int idx = tid; idx < 8192; idx += 256) {
        int t = idx & 63;
        xs[idx] = (t < 62) ? xin[idx] : 0.f;
    }
    __syncthreads();

    int lg = tid & 31, tg = tid >> 5;
    float m[4] = {-1e30f, -1e30f, -1e30f, -1e30f};
    #pragma unroll
    for (int half = 0; half < 2; half++) {
        int tb = tg*4 + 32*half;
        float acc[4][4];
        #pragma unroll
        for (int a1 = 0; a1 < 4; a1++)
            #pragma unroll
            for (int a2 = 0; a2 < 4; a2++) acc[a1][a2] = 0.f;
        for (int c = 0; c < 128; c++) {
            float x0 = xs[c*64 + tb    ], x1 = xs[c*64 + tb + 1];
            float x2 = xs[c*64 + tb + 2], x3 = xs[c*64 + tb + 3];
            #pragma unroll
            for (int il = 0; il < 4; il++) {
                float w = wts[c*128 + lg + 32*il];
                acc[il][0] = fmaf(w, x0, acc[il][0]);
                acc[il][1] = fmaf(w, x1, acc[il][1]);
                acc[il][2] = fmaf(w, x2, acc[il][2]);
                acc[il][3] = fmaf(w, x3, acc[il][3]);
            }
        }
        #pragma unroll
        for (int il = 0; il < 4; il++)
            #pragma unroll
            for (int tt = 0; tt < 4; tt++)
                if (tb + tt < 62) m[il] = fmaxf(m[il], acc[il][tt]);
    }
    #pragma unroll
    for (int il = 0; il < 4; il++) red[tg*128 + lg + 32*il] = m[il];
    __syncthreads();
    if (tid < 128) {
        float y = red[tid];
        #pragma unroll
        for (int t2 = 1; t2 < 8; t2++) y = fmaxf(y, red[t2*128 + tid]);
        y += b_fc[lt*128 + tid];
        g_y[(size_t)(i*NB + b)*1024 + lt*128 + tid] = y;
    }
}

// ---------------- stage 8: normalize + dot ----------------
__global__ __launch_bounds__(256) void k_final(float* __restrict__ out) {
    __shared__ float r1[256], r2[256];
    int b = blockIdx.x, i = blockIdx.y, tid = threadIdx.x;
    const float* y = g_y + (size_t)(i*NB + b)*1024;
    const float* g = g_img_global + i*LL;
    float d = 0.f, ss = 0.f;
    for (int l = tid; l < 1024; l += 256) { float yv = y[l]; d = fmaf(yv, g[l], d); ss = fmaf(yv, yv, ss); }
    r1[tid] = d; r2[tid] = ss; __syncthreads();
    for (int s = 128; s > 0; s >>= 1) {
        if (tid < s) { r1[tid] += r1[tid+s]; r2[tid] += r2[tid+s]; }
        __syncthreads();
    }
    if (tid == 0) out[i*NB + b] = r1[0] / (sqrtf(r2[0]) * g_inorm[i]);
}

// ---------------- launch ----------------
extern "C" void kernel_launch(void* const* d_in, const int* in_sizes, int n_in,
                              void* d_out, int out_size) {
    (void)in_sizes; (void)n_in; (void)out_size;
    const float* img_embed = (const float*)d_in[0];
    const float* cap_embed = (const float*)d_in[1];
    const float* W_ri = (const float*)d_in[2];
    const float* b_ri = (const float*)d_in[3];
    const float* W_rt = (const float*)d_in[4];
    const float* b_rt = (const float*)d_in[5];
    const float* mk_W = (const float*)d_in[6];
    const float* mk_b = (const float*)d_in[7];
    // d_in[8]=mbias_W, d_in[9]=mbias_b, d_in[13]=ca_b: exactly cancelled by training-mode BN
    const float* wn_g = (const float*)d_in[10];
    const float* wn_b = (const float*)d_in[11];
    const float* ca_W = (const float*)d_in[12];
    const float* bn_g = (const float*)d_in[14];
    const float* bn_b = (const float*)d_in[15];
    const float* c1_W = (const float*)d_in[16];
    const float* c1_b = (const float*)d_in[17];
    const float* W_fc = (const float*)d_in[18];
    const float* b_fc = (const float*)d_in[19];
    float* out = (float*)d_out;

    const int CAP_SMEM  = 300*64*4;
    const int GEN_SMEM  = (128 + 16384)*4;
    const int CONV_SMEM = (8192 + 16384 + 16384)*4;
    const int C1_SMEM   = (16384 + 32768 + 512)*4;
    const int FC_SMEM   = (16384 + 8192 + 1024)*4;
    cudaFuncSetAttribute((const void*)k_cap_red,  cudaFuncAttributeMaxDynamicSharedMemorySize, CAP_SMEM);
    cudaFuncSetAttribute((const void*)k_gen,      cudaFuncAttributeMaxDynamicSharedMemorySize, GEN_SMEM);
    cudaFuncSetAttribute((const void*)k_conv<63>, cudaFuncAttributeMaxDynamicSharedMemorySize, CONV_SMEM);
    cudaFuncSetAttribute((const void*)k_conv<62>, cudaFuncAttributeMaxDynamicSharedMemorySize, CONV_SMEM);
    cudaFuncSetAttribute((const void*)k_c1<63>,   cudaFuncAttributeMaxDynamicSharedMemorySize, C1_SMEM);
    cudaFuncSetAttribute((const void*)k_c1<62>,   cudaFuncAttributeMaxDynamicSharedMemorySize, C1_SMEM);
    cudaFuncSetAttribute((const void*)k_fc_max,   cudaFuncAttributeMaxDynamicSharedMemorySize, FC_SMEM);

    k_img_prep<<<NI, 256>>>(img_embed, W_ri, b_ri);
    k_cap_red<<<NB, 256, CAP_SMEM>>>(cap_embed, W_rt, b_rt);
    k_gen<<<NI*2, 256, GEN_SMEM>>>(mk_W, mk_b, wn_g, wn_b);
    k_transpose<<<256, 256>>>(W_fc, c1_W, ca_W);

    // block j = 0 (T 64 -> 63)
    k_zero_stats<<<64, 256>>>();
    k_conv<63><<<dim3(NB, NI), 256, CONV_SMEM>>>(0);
    k_c1<63><<<dim3(NB, NI), 256, C1_SMEM>>>(bn_g, bn_b, c1_b, 0);

    // block j = 1 (T 63 -> 62)
    k_zero_stats<<<64, 256>>>();
    k_conv<62><<<dim3(NB, NI), 256, CONV_SMEM>>>(1);
    k_c1<62><<<dim3(NB, NI), 256, C1_SMEM>>>(bn_g, bn_b, c1_b, 1);

    // W_fc + max over time, then normalize + dot
    k_fc_max<<<dim3(8, NB, NI), 256, FC_SMEM>>>(b_fc);
    k_final<<<dim3(NB, NI), 256>>>(out);
}

// round 2
// speedup vs baseline: 1.1210x; 1.1210x over previous
#include <cuda_runtime.h>
#include <math.h>

#define NI 32     // images
#define NB 128    // captions
#define RR 128    // reduced channels
#define LL 1024   // latent
#define TT 64     // initial time

typedef unsigned long long u64;

// ---------------- packed f32x2 helpers (sm_103a FFMA2 path) ----------------
__device__ __forceinline__ u64 pk2(float lo, float hi) {
    u64 v; asm("mov.b64 %0, {%1, %2};" : "=l"(v) : "f"(lo), "f"(hi)); return v;
}
__device__ __forceinline__ u64 bc2(float x) { return pk2(x, x); }
__device__ __forceinline__ void up2(u64 v, float& lo, float& hi) {
    asm("mov.b64 {%0, %1}, %2;" : "=f"(lo), "=f"(hi) : "l"(v));
}
__device__ __forceinline__ u64 fma2(u64 a, u64 b, u64 c) {
    u64 d; asm("fma.rn.f32x2 %0, %1, %2, %3;" : "=l"(d) : "l"(a), "l"(b), "l"(c)); return d;
}

// ---------------- device scratch (static globals; no allocation) ----------------
__device__ float  g_cap_red[NB*RR*TT];                 // [b][o][64]
__device__ float  g_img_global[NI*LL];
__device__ float  g_inorm[NI];
__device__ float  g_img_vec[NI*RR];
__device__ float  g_kern[NI*2*128*128];                // [(i*2+j)][cik][o]
__device__ float  g_caWT[2*128*128];                   // [j][cik][o]
__device__ float  g_c1WT[2*256*128];                   // [j][ch][o]
__device__ float  g_WfcT[128*1024];                    // [c][l]
__device__ double g_stats[2*NI*512];                   // per-j per-image per-channel sum/sumsq
__device__ float  g_h[(size_t)NI*NB*256*64];           // conv outputs (px|ax)
__device__ float  g_x[(size_t)NI*NB*128*64];           // block activations
__device__ float  g_y[(size_t)NI*NB*1024];             // max-pooled pre-norm

// ---------------- stage 1: image prep (mean, norm, hypernet base) ----------------
__global__ __launch_bounds__(256) void k_img_prep(const float* __restrict__ img_embed,
                                                  const float* __restrict__ W_ri,
                                                  const float* __restrict__ b_ri) {
    __shared__ float gsh[LL];
    __shared__ float red[256];
    int i = blockIdx.x, tid = threadIdx.x;
    float ssq = 0.f;
    for (int c = tid; c < LL; c += 256) {
        float s = 0.f;
        #pragma unroll
        for (int t = 0; t < 36; t++) s += img_embed[((size_t)i*36 + t)*LL + c];
        s *= (1.0f/36.0f);
        gsh[c] = s;
        g_img_global[i*LL + c] = s;
        ssq += s*s;
    }
    red[tid] = ssq; __syncthreads();
    for (int s = 128; s > 0; s >>= 1) { if (tid < s) red[tid] += red[tid+s]; __syncthreads(); }
    if (tid == 0) g_inorm[i] = sqrtf(red[0]);
    if (tid < RR) {
        int o = tid;
        float acc = b_ri[o];
        const float* w = W_ri + (size_t)o * LL;
        for (int c = 0; c < LL; c++) acc = fmaf(w[c], gsh[c], acc);
        g_img_vec[i*RR + o] = acc;
    }
}

// ---------------- stage 2: hypernet kernel generation + weight BN (+ stats zero) ----
__global__ __launch_bounds__(256) void k_gen(const float* __restrict__ mk_W,
                                             const float* __restrict__ mk_b,
                                             const float* __restrict__ wn_g,
                                             const float* __restrict__ wn_b) {
    extern __shared__ float sm[];
    float* base = sm;          // 128
    float* kraw = sm + 128;    // 16384
    int i = blockIdx.x >> 1, j = blockIdx.x & 1, tid = threadIdx.x;
    // zero BN-stat accumulators for both blocks (consumed by later launches)
    for (int z = blockIdx.x*256 + tid; z < 2*NI*512; z += 64*256) g_stats[z] = 0.0;
    if (tid < RR) base[tid] = g_img_vec[i*RR + tid];
    __syncthreads();
    for (int f = tid; f < 16384; f += 256) {
        float acc = mk_b[j*16384 + f];
        const float* w = mk_W + ((size_t)j*16384 + f)*128;
        #pragma unroll 4
        for (int c = 0; c < 128; c++) acc = fmaf(w[c], base[c], acc);
        kraw[f] = acc;
    }
    __syncthreads();
    if (tid < RR) {
        int o = tid;
        const float* kr = kraw + o*128;
        float s = 0.f, s2 = 0.f;
        for (int c = 0; c < 128; c++) { float v = kr[c]; s += v; s2 += v*v; }
        float m   = s * (1.f/128.f);
        float var = s2 * (1.f/128.f) - m*m;
        float a   = wn_g[j*RR+o] * rsqrtf(var + 1e-5f);
        float bb  = wn_b[j*RR+o] - a*m;
        float* dst = g_kern + ((size_t)(i*2+j))*16384;    // [cik][o]
        for (int cik = 0; cik < 128; cik++) dst[cik*128 + o] = fmaf(a, kr[cik], bb);
    }
}

// ---------------- stage 3: caption reduction (1x1 conv 300->128) + weight transposes --
__global__ __launch_bounds__(256) void k_cap_red(const float* __restrict__ cap_embed,
                                                 const float* __restrict__ W_rt,
                                                 const float* __restrict__ b_rt,
                                                 const float* __restrict__ W_fc,
                                                 const float* __restrict__ c1_W,
                                                 const float* __restrict__ ca_W) {
    extern __shared__ float sm[];
    float* ce = sm;                      // [c 300][t 64]
    int b = blockIdx.x, tid = threadIdx.x;
    // fused transposes (grid-stride over all blocks)
    {
        const int N1 = 128*1024, N2 = 2*256*128, N3 = 2*128*128;
        for (int t = b*256 + tid; t < N1+N2+N3; t += NB*256) {
            if (t < N1) {
                int c = t >> 10, l = t & 1023;
                g_WfcT[t] = W_fc[l*128 + c];
            } else if (t < N1+N2) {
                int u = t - N1;
                int j = u >> 15; int v = u & 32767; int ch = v >> 7, o = v & 127;
                g_c1WT[u] = c1_W[(j*128 + o)*256 + ch];
            } else {
                int u = t - N1 - N2;
                int j = u >> 14; int v = u & 16383; int cik = v >> 7, o = v & 127;
                g_caWT[u] = ca_W[(j*128 + o)*128 + cik];
            }
        }
    }
    for (int idx = tid; idx < 300*TT; idx += 256) {
        int c = idx >> 6, t = idx & 63;
        ce[idx] = cap_embed[(size_t)b*TT*300 + t*300 + c];
    }
    __syncthreads();
    for (int q = tid; q < RR*16; q += 256) {
        int o = q >> 4, tq = (q & 15) * 4;
        float a0 = 0.f, a1 = 0.f, a2 = 0.f, a3 = 0.f;
        const float* w = W_rt + o*300;
        for (int c = 0; c < 300; c++) {
            float wv = w[c];
            float4 x4 = *(const float4*)(ce + c*TT + tq);
            a0 = fmaf(wv, x4.x, a0); a1 = fmaf(wv, x4.y, a1);
            a2 = fmaf(wv, x4.z, a2); a3 = fmaf(wv, x4.w, a3);
        }
        float bo = b_rt[o];
        float* dst = g_cap_red + ((size_t)b*RR + o)*TT + tq;
        dst[0] = a0 + bo; dst[1] = a1 + bo; dst[2] = a2 + bo; dst[3] = a3 + bo;
    }
}

// ---------------- stage 4: grouped convs (px = hypernet, ax = static) + BN stats ----
// thread owns an o-PAIR (f32x2 on output channels) for both convs; x broadcast-packed
template<int TOUT>
__global__ __launch_bounds__(256) void k_conv(int j) {
    extern __shared__ float sm[];
    float* xs  = sm;                    // [128][64]
    float* wpx = sm + 8192;             // [cik][o]
    float* wax = sm + 8192 + 16384;     // [cik][o]
    int b = blockIdx.x, i = blockIdx.y, tid = threadIdx.x;
    const float* xin = (j == 0) ? (g_cap_red + (size_t)b*8192)
                                : (g_x + ((size_t)i*NB + b)*8192);
    for (int idx = tid; idx < 8192; idx += 256) xs[idx] = xin[idx];
    const float* kp = g_kern + (size_t)(i*2 + j)*16384;
    const float* ka = g_caWT + (size_t)j*16384;
    for (int idx = tid; idx < 16384; idx += 256) { wpx[idx] = kp[idx]; wax[idx] = ka[idx]; }
    __syncthreads();

    int opair = tid & 63, th = tid >> 6;       // 64 o-pairs x 4 t-slots
    const float* xg = xs + (opair >> 5) * 4096;
    const int wo = opair * 2;
    float sp0=0.f, sp0q=0.f, sp1=0.f, sp1q=0.f;
    float sa0=0.f, sa0q=0.f, sa1=0.f, sa1q=0.f;

    for (int chunk = th; chunk < 8; chunk += 4) {
        int t0 = chunk * 8;
        u64 accP[8], accA[8];
        #pragma unroll
        for (int t = 0; t < 8; t++) { accP[t] = 0ull; accA[t] = 0ull; }
        #pragma unroll 2
        for (int ci = 0; ci < 64; ci++) {
            const float* xr = xg + ci*64 + t0;
            float4 xlo = *(const float4*)xr;
            float4 xhi = *(const float4*)(xr + 4);
            float x8v = xr[8];   // last chunk reads 1 past row; result discarded below
            u64 xx[9];
            xx[0]=bc2(xlo.x); xx[1]=bc2(xlo.y); xx[2]=bc2(xlo.z); xx[3]=bc2(xlo.w);
            xx[4]=bc2(xhi.x); xx[5]=bc2(xhi.y); xx[6]=bc2(xhi.z); xx[7]=bc2(xhi.w);
            xx[8]=bc2(x8v);
            u64 wp0 = *(const u64*)(wpx + (ci*2  )*128 + wo);
            u64 wp1 = *(const u64*)(wpx + (ci*2+1)*128 + wo);
            u64 wa0 = *(const u64*)(wax + (ci*2  )*128 + wo);
            u64 wa1 = *(const u64*)(wax + (ci*2+1)*128 + wo);
            #pragma unroll
            for (int t = 0; t < 8; t++) {
                accP[t] = fma2(wp0, xx[t],   accP[t]);
                accP[t] = fma2(wp1, xx[t+1], accP[t]);
                accA[t] = fma2(wa0, xx[t],   accA[t]);
                accA[t] = fma2(wa1, xx[t+1], accA[t]);
            }
        }
        float* hp = g_h + ((size_t)(i*NB + b))*16384;   // [256 ch][64 t]
        #pragma unroll
        for (int t = 0; t < 8; t++) {
            int tg = t0 + t;
            if (tg < TOUT) {
                float p0, p1, a0, a1;
                up2(accP[t], p0, p1);
                up2(accA[t], a0, a1);
                hp[(wo  )*64 + tg] = p0;
                hp[(wo+1)*64 + tg] = p1;
                hp[(128+wo  )*64 + tg] = a0;
                hp[(128+wo+1)*64 + tg] = a1;
                sp0 += p0; sp0q += p0*p0; sp1 += p1; sp1q += p1*p1;
                sa0 += a0; sa0q += a0*a0; sa1 += a1; sa1q += a1*a1;
            }
        }
    }
    double* st = g_stats + ((size_t)j*NI + i)*512;
    atomicAdd(st + (wo      )*2    , (double)sp0);
    atomicAdd(st + (wo      )*2 + 1, (double)sp0q);
    atomicAdd(st + (wo+1    )*2    , (double)sp1);
    atomicAdd(st + (wo+1    )*2 + 1, (double)sp1q);
    atomicAdd(st + (128+wo  )*2    , (double)sa0);
    atomicAdd(st + (128+wo  )*2 + 1, (double)sa0q);
    atomicAdd(st + (128+wo+1)*2    , (double)sa1);
    atomicAdd(st + (128+wo+1)*2 + 1, (double)sa1q);
}

// ---------------- stage 5: BN+ReLU fused into 1x1 mixing conv (c1), f32x2 ----------
template<int TOUT>
__global__ __launch_bounds__(256) void k_c1(const float* __restrict__ bn_g,
                                            const float* __restrict__ bn_b,
                                            const float* __restrict__ c1_b, int j) {
    extern __shared__ float sm[];
    float* hs = sm;                       // [256][64]
    float* ws = sm + 16384;               // [ch][o]
    float* aa = sm + 49152;               // 256
    float* bb = sm + 49408;               // 256
    int b = blockIdx.x, i = blockIdx.y, tid = threadIdx.x;
    {
        double s  = g_stats[((size_t)j*NI + i)*512 + tid*2];
        double s2 = g_stats[((size_t)j*NI + i)*512 + tid*2 + 1];
        double n  = (double)(NB*TOUT);
        float m   = (float)(s / n);
        float var = (float)(s2 / n) - m*m;
        float a   = bn_g[j*256 + tid] * rsqrtf(var + 1e-5f);
        aa[tid] = a;
        bb[tid] = bn_b[j*256 + tid] - a*m;
    }
    __syncthreads();
    const float* hsrc = g_h + (size_t)(i*NB + b)*16384;
    for (int idx = tid; idx < 16384; idx += 256) {
        int ch = idx >> 6, t = idx & 63;
        float v = fmaf(aa[ch], hsrc[idx], bb[ch]);
        hs[idx] = (t < TOUT) ? fmaxf(v, 0.f) : 0.f;
    }
    const float* wsrc = g_c1WT + j*32768;
    for (int idx = tid; idx < 32768; idx += 256) ws[idx] = wsrc[idx];
    __syncthreads();

    int lane = tid & 31, wp = tid >> 5;
    int t0 = wp * 8;
    u64 acc0[8], acc1[8];
    #pragma unroll
    for (int t = 0; t < 8; t++) { acc0[t] = 0ull; acc1[t] = 0ull; }
    #pragma unroll 2
    for (int ch = 0; ch < 256; ch++) {
        u64 w0 = *(const u64*)(ws + ch*128 + 2*lane);
        u64 w1 = *(const u64*)(ws + ch*128 + 64 + 2*lane);
        float4 xa = *(const float4*)(hs + ch*64 + t0);
        float4 xb = *(const float4*)(hs + ch*64 + t0 + 4);
        u64 xx[8];
        xx[0]=bc2(xa.x); xx[1]=bc2(xa.y); xx[2]=bc2(xa.z); xx[3]=bc2(xa.w);
        xx[4]=bc2(xb.x); xx[5]=bc2(xb.y); xx[6]=bc2(xb.z); xx[7]=bc2(xb.w);
        #pragma unroll
        for (int t = 0; t < 8; t++) {
            acc0[t] = fma2(w0, xx[t], acc0[t]);
            acc1[t] = fma2(w1, xx[t], acc1[t]);
        }
    }
    float* xout = g_x + (size_t)(i*NB + b)*8192;
    int oA = 2*lane, oB = 64 + 2*lane;
    float cbA0 = c1_b[j*128+oA],   cbA1 = c1_b[j*128+oA+1];
    float cbB0 = c1_b[j*128+oB],   cbB1 = c1_b[j*128+oB+1];
    #pragma unroll
    for (int t = 0; t < 8; t++) {
        int tg = t0 + t;
        if (tg < TOUT) {
            float lo, hi;
            up2(acc0[t], lo, hi);
            xout[oA*64 + tg] = lo + cbA0; xout[(oA+1)*64 + tg] = hi + cbA1;
            up2(acc1[t], lo, hi);
            xout[oB*64 + tg] = lo + cbB0; xout[(oB+1)*64 + tg] = hi + cbB1;
        }
    }
}

// ---------------- stage 6: W_fc GEMM fused with max-over-time, f32x2 ----------------
__global__ __launch_bounds__(256) void k_fc_max(const float* __restrict__ b_fc) {
    extern __shared__ float sm[];
    float* wts = sm;                  // [c 128][l 128]
    float* xs  = sm + 16384;          // [c 128][t 64]
    float* red = sm + 16384 + 8192;   // [warp 8][l 128]
    int lt = blockIdx.x, b = blockIdx.y, i = blockIdx.z, tid = threadIdx.x;
    for (int idx = tid; idx < 16384; idx += 256) {
        int c = idx >> 7, l = idx & 127;
        wts[idx] = g_WfcT[c*1024 + lt*128 + l];
    }
    const float* xin = g_x + (size_t)(i*NB + b)*8192;
    for (int idx = tid; idx < 8192; idx += 256) {
        int t = idx & 63;
        xs[idx] = (t < 62) ? xin[idx] : 0.f;
    }
    __syncthreads();

    int lane = tid & 31, wp = tid >> 5;
    int t0 = wp * 8;
    u64 acc0[8], acc1[8];
    #pragma unroll
    for (int t = 0; t < 8; t++) { acc0[t] = 0ull; acc1[t] = 0ull; }
    #pragma unroll 2
    for (int c = 0; c < 128; c++) {
        u64 w0 = *(const u64*)(wts + c*128 + 2*lane);
        u64 w1 = *(const u64*)(wts + c*128 + 64 + 2*lane);
        float4 xa = *(const float4*)(xs + c*64 + t0);
        float4 xb = *(const float4*)(xs + c*64 + t0 + 4);
        u64 xx[8];
        xx[0]=bc2(xa.x); xx[1]=bc2(xa.y); xx[2]=bc2(xa.z); xx[3]=bc2(xa.w);
        xx[4]=bc2(xb.x); xx[5]=bc2(xb.y); xx[6]=bc2(xb.z); xx[7]=bc2(xb.w);
        #pragma unroll
        for (int t = 0; t < 8; t++) {
            acc0[t] = fma2(w0, xx[t], acc0[t]);
            acc1[t] = fma2(w1, xx[t], acc1[t]);
        }
    }
    float m0 = -1e30f, m1 = -1e30f, m2 = -1e30f, m3 = -1e30f;
    #pragma unroll
    for (int t = 0; t < 8; t++) {
        if (t0 + t < 62) {
            float lo, hi;
            up2(acc0[t], lo, hi); m0 = fmaxf(m0, lo); m1 = fmaxf(m1, hi);
            up2(acc1[t], lo, hi); m2 = fmaxf(m2, lo); m3 = fmaxf(m3, hi);
        }
    }
    red[wp*128 + 2*lane    ] = m0;
    red[wp*128 + 2*lane + 1] = m1;
    red[wp*128 + 64 + 2*lane    ] = m2;
    red[wp*128 + 64 + 2*lane + 1] = m3;
    __syncthreads();
    if (tid < 128) {
        float y = red[tid];
        #pragma unroll
        for (int w2 = 1; w2 < 8; w2++) y = fmaxf(y, red[w2*128 + tid]);
        y += b_fc[lt*128 + tid];
        g_y[(size_t)(i*NB + b)*1024 + lt*128 + tid] = y;
    }
}

// ---------------- stage 7: normalize + dot ----------------
__global__ __launch_bounds__(256) void k_final(float* __restrict__ out) {
    __shared__ float r1[256], r2[256];
    int b = blockIdx.x, i = blockIdx.y, tid = threadIdx.x;
    const float* y = g_y + (size_t)(i*NB + b)*1024;
    const float* g = g_img_global + i*LL;
    float d = 0.f, ss = 0.f;
    for (int l = tid; l < 1024; l += 256) { float yv = y[l]; d = fmaf(yv, g[l], d); ss = fmaf(yv, yv, ss); }
    r1[tid] = d; r2[tid] = ss; __syncthreads();
    for (int s = 128; s > 0; s >>= 1) {
        if (tid < s) { r1[tid] += r1[tid+s]; r2[tid] += r2[tid+s]; }
        __syncthreads();
    }
    if (tid == 0) out[i*NB + b] = r1[0] / (sqrtf(r2[0]) * g_inorm[i]);
}

// ---------------- launch ----------------
extern "C" void kernel_launch(void* const* d_in, const int* in_sizes, int n_in,
                              void* d_out, int out_size) {
    (void)in_sizes; (void)n_in; (void)out_size;
    const float* img_embed = (const float*)d_in[0];
    const float* cap_embed = (const float*)d_in[1];
    const float* W_ri = (const float*)d_in[2];
    const float* b_ri = (const float*)d_in[3];
    const float* W_rt = (const float*)d_in[4];
    const float* b_rt = (const float*)d_in[5];
    const float* mk_W = (const float*)d_in[6];
    const float* mk_b = (const float*)d_in[7];
    // d_in[8]=mbias_W, d_in[9]=mbias_b, d_in[13]=ca_b: exactly cancelled by training-mode BN
    const float* wn_g = (const float*)d_in[10];
    const float* wn_b = (const float*)d_in[11];
    const float* ca_W = (const float*)d_in[12];
    const float* bn_g = (const float*)d_in[14];
    const float* bn_b = (const float*)d_in[15];
    const float* c1_W = (const float*)d_in[16];
    const float* c1_b = (const float*)d_in[17];
    const float* W_fc = (const float*)d_in[18];
    const float* b_fc = (const float*)d_in[19];
    float* out = (float*)d_out;

    const int CAP_SMEM  = 300*64*4;
    const int GEN_SMEM  = (128 + 16384)*4;
    const int CONV_SMEM = (8192 + 16384 + 16384)*4;
    const int C1_SMEM   = (16384 + 32768 + 512)*4;
    const int FC_SMEM   = (16384 + 8192 + 1024)*4;
    cudaFuncSetAttribute((const void*)k_cap_red,  cudaFuncAttributeMaxDynamicSharedMemorySize, CAP_SMEM);
    cudaFuncSetAttribute((const void*)k_gen,      cudaFuncAttributeMaxDynamicSharedMemorySize, GEN_SMEM);
    cudaFuncSetAttribute((const void*)k_conv<63>, cudaFuncAttributeMaxDynamicSharedMemorySize, CONV_SMEM);
    cudaFuncSetAttribute((const void*)k_conv<62>, cudaFuncAttributeMaxDynamicSharedMemorySize, CONV_SMEM);
    cudaFuncSetAttribute((const void*)k_c1<63>,   cudaFuncAttributeMaxDynamicSharedMemorySize, C1_SMEM);
    cudaFuncSetAttribute((const void*)k_c1<62>,   cudaFuncAttributeMaxDynamicSharedMemorySize, C1_SMEM);
    cudaFuncSetAttribute((const void*)k_fc_max,   cudaFuncAttributeMaxDynamicSharedMemorySize, FC_SMEM);

    k_img_prep<<<NI, 256>>>(img_embed, W_ri, b_ri);
    k_gen<<<NI*2, 256, GEN_SMEM>>>(mk_W, mk_b, wn_g, wn_b);
    k_cap_red<<<NB, 256, CAP_SMEM>>>(cap_embed, W_rt, b_rt, W_fc, c1_W, ca_W);

    // block j = 0 (T 64 -> 63)
    k_conv<63><<<dim3(NB, NI), 256, CONV_SMEM>>>(0);
    k_c1<63><<<dim3(NB, NI), 256, C1_SMEM>>>(bn_g, bn_b, c1_b, 0);

    // block j = 1 (T 63 -> 62)
    k_conv<62><<<dim3(NB, NI), 256, CONV_SMEM>>>(1);
    k_c1<62><<<dim3(NB, NI), 256, C1_SMEM>>>(bn_g, bn_b, c1_b, 1);

    // W_fc + max over time, then normalize + dot
    k_fc_max<<<dim3(8, NB, NI), 256, FC_SMEM>>>(b_fc);
    k_final<<<dim3(NB, NI), 256>>>(out);
}